// round 15
// baseline (speedup 1.0000x reference)
#include <cuda_runtime.h>

typedef unsigned long long u64;
typedef unsigned int u32;

#define NB        8
#define NCLS      80
#define NCLASSES  (NB * NCLS)      // 640
#define KCAND     256
#define MAXPC     8
#define CSTRIDE32 1280             // u32 slots per class (= 640 u64 fallback view)
#define CAPSC     64               // trusted capture bound (E=32, Poisson)
#define KRC       2                // u32 keys/lane = 64 sorted slots
#define KRF       20               // u64 keys/lane, fallback
#define LOCCAP    8
#define NCHUNKS   74               // grid = 8*74 = 592 = exactly 4 CTAs/SM * 148
#define THR       0.99841f         // E[captures/class] = 32
#define SBASE     0x3F7F0000u
#define NBUCKETS  1024
#define BATCH     16
#define UNR       8
#define FULLM     0xFFFFFFFFu

static __device__ u32    g_cand[NCLASSES * CSTRIDE32];  // 3.3 MB scratch
static __device__ int    g_cnt[NCLASSES];               // reset by CTA0 each launch
static __device__ u64    g_keys[NCLASSES * MAXPC];
static __device__ float4 g_boxes[NCLASSES * MAXPC];
static __device__ u32    g_hist[NCLASSES * NBUCKETS];   // fallback-only scratch
static __device__ int    g_nmsdone[NB];                 // per-batch NMS completion
static __device__ volatile u32 g_bar1;                  // reset by CTA0 each launch

__device__ __forceinline__ float clamp01(float x) { return fminf(fmaxf(x, 0.0f), 1.0f); }

__device__ __forceinline__ u64 warpmax64(u64 v)
{
    u32 hi = (u32)(v >> 32);
    u32 hmax = __reduce_max_sync(FULLM, hi);
    u32 lo = (hi == hmax) ? (u32)v : 0u;
    u32 lmax = __reduce_max_sync(FULLM, lo);
    return ((u64)hmax << 32) | lmax;
}

// full resident-grid barrier (co-residency: launch_bounds(256,4), grid = 4*148)
__device__ __forceinline__ void grid_barrier(volatile u32* bar, u32 target)
{
    __syncthreads();
    if (threadIdx.x == 0) {
        __threadfence();
        atomicAdd((u32*)bar, 1u);
        while (*bar < target) __nanosleep(64);
        __threadfence();
    }
    __syncthreads();
}

// ---------------------------------------------------------------------------
// Common path: bitonic-sort 64 u32 keys in registers, then greedy NMS in
// exact rank order. Minimal collectives: no per-pop key shuffle, deferred
// key fetch, stores after the loop. *ranout true iff exit without 8 keeps.
// ---------------------------------------------------------------------------
__device__ int nms_sorted(const float4* __restrict__ boxes4, int nbox, int b, int c,
                          const u32* __restrict__ cand, int cnt, bool* ranout)
{
    const int lane = threadIdx.x & 31;

    u32 kr[KRC];
    kr[0] = (lane < cnt) ? cand[lane] : 0u;
    kr[1] = (32 + lane < cnt) ? cand[32 + lane] : 0u;

    // bitonic sort, 64 elements, descending; element e = lane + 32*r
    #pragma unroll
    for (int size = 2; size <= 64; size <<= 1) {
        #pragma unroll
        for (int stride = size >> 1; stride > 0; stride >>= 1) {
            if (stride >= 32) {     // only stride=32: in-register pair (r=0, r=1)
                const int e = lane;
                const bool descB = ((e & size) == 0);
                u32 a = kr[0], d = kr[1];
                u32 mx = a > d ? a : d, mn = a > d ? d : a;
                kr[0] = descB ? mx : mn;
                kr[1] = descB ? mn : mx;
            } else {
                #pragma unroll
                for (int r = 0; r < KRC; ++r) {
                    const int e = lane + 32 * r;
                    u32 other = __shfl_xor_sync(FULLM, kr[r], stride);
                    const bool iLow  = (lane & stride) == 0;
                    const bool descB = ((e & size) == 0);
                    const bool keepMax = (iLow == descB);
                    u32 mx = kr[r] > other ? kr[r] : other;
                    u32 mn = kr[r] > other ? other : kr[r];
                    kr[r] = keepMax ? mx : mn;
                }
            }
        }
    }
    // sorted: rank g*32 + lane lives in kr[g] at this lane (keys never clobbered)

    float4 mykept = make_float4(0.f, 0.f, 0.f, 0.f);
    float  myka   = 0.f;
    int    myrank = 0;
    int kc = 0;
    bool done = false;

    #pragma unroll
    for (int g = 0; g < KRC; ++g) {
        if (done) break;
        const int gcnt = min(32, cnt - g * 32);   // uniform; loop bound, no key shfl
        if (gcnt <= 0) break;
        u32 kg = kr[g];
        float4 obox = make_float4(0.f, 0.f, 0.f, 0.f);
        if (lane < gcnt) {
            u32 bi = 0x7FFFu - (kg & 0x7FFFu);
            obox = boxes4[(size_t)b * nbox + bi];
        }
        for (int r = 0; r < gcnt; ++r) {
            float4 bx;
            bx.x = __shfl_sync(FULLM, obox.x, r);
            bx.y = __shfl_sync(FULLM, obox.y, r);
            bx.z = __shfl_sync(FULLM, obox.z, r);
            bx.w = __shfl_sync(FULLM, obox.w, r);
            float area = fmaxf(bx.z - bx.x, 0.f) * fmaxf(bx.w - bx.y, 0.f);

            bool supme = false;
            if (lane < kc) {
                float iy1 = fmaxf(bx.x, mykept.x), ix1 = fmaxf(bx.y, mykept.y);
                float iy2 = fminf(bx.z, mykept.z), ix2 = fminf(bx.w, mykept.w);
                float inter = fmaxf(iy2 - iy1, 0.f) * fmaxf(ix2 - ix1, 0.f);
                float uni = area + myka - inter;
                float iou = (uni > 0.f) ? inter / uni : 0.f;
                supme = iou > 0.5f;
            }
            bool keep = (__ballot_sync(FULLM, supme) == 0u);   // uniform

            if (keep) {
                if (lane == kc) { mykept = bx; myka = area; myrank = g * 32 + r; }
                ++kc;
                if (kc >= MAXPC) { done = true; break; }       // uniform
            }
        }
    }

    // deferred key fetch for kept lanes: 2 shuffles total (uniform execution)
    {
        int rk = myrank & 31;
        u32 k0 = __shfl_sync(FULLM, kr[0], rk);
        u32 k1 = __shfl_sync(FULLM, kr[1], rk);
        if (lane < kc) {
            u32 key = (myrank & 32) ? k1 : k0;
            int flat = c * KCAND + myrank;
            int pos  = c * MAXPC + lane;    // kept slot == lane
            g_keys[b * NCLS * MAXPC + pos] =
                ((u64)((key >> 15) + SBASE) << 32) |
                ((u64)(u32)(0x7FFF - flat) << 16) | (u32)pos;
            g_boxes[b * NCLS * MAXPC + pos] = mykept;
        }
    }
    *ranout = (kc < MAXPC);   // <=64 pops can never legitimately hit the 256 cap
    return kc;
}

// ---------------------------------------------------------------------------
// Fallback path (u64 keys, REDUX pops) — exact, never expected.
// ---------------------------------------------------------------------------
__device__ int run_nms_fb(const float4* __restrict__ boxes4, int nbox, int b, int c,
                          const u64* __restrict__ cand, int cnt)
{
    const int lane = threadIdx.x & 31;

    u64 kr[KRF];
    #pragma unroll
    for (int r = 0; r < KRF; ++r) {
        int slot = r * 32 + lane;
        kr[r] = (slot < cnt) ? cand[slot] : 0ull;
    }
    u64 mymax = kr[0];
    #pragma unroll
    for (int r = 1; r < KRF; ++r) if (kr[r] > mymax) mymax = kr[r];

    float4 mykept = make_float4(0.f, 0.f, 0.f, 0.f);
    float  myka   = 0.f;
    int kc = 0, totpops = 0;
    bool more = true;

    while (more && kc < MAXPC && totpops < KCAND) {
        const int lim = min(BATCH, KCAND - totpops);
        u64 okey = 0ull;
        int n = 0;
        for (int r = 0; r < lim; ++r) {
            u64 best = warpmax64(mymax);
            if ((u32)(best >> 32) <= 0x3F000000u) break;
            if (lane == r) okey = best;
            if (mymax == best) {
                mymax = 0ull;
                #pragma unroll
                for (int q = 0; q < KRF; ++q) {
                    if (kr[q] == best) kr[q] = 0ull;
                    if (kr[q] > mymax) mymax = kr[q];
                }
            }
            ++n;
        }
        more = (n == lim) && (lim == BATCH);

        float4 obox = make_float4(0.f, 0.f, 0.f, 0.f);
        if (lane < n)
            obox = boxes4[(size_t)b * nbox + (0xFFFFFFFFu - (u32)okey)];

        for (int r = 0; r < n; ++r) {
            float4 bx;
            bx.x = __shfl_sync(FULLM, obox.x, r);
            bx.y = __shfl_sync(FULLM, obox.y, r);
            bx.z = __shfl_sync(FULLM, obox.z, r);
            bx.w = __shfl_sync(FULLM, obox.w, r);
            u64 key = __shfl_sync(FULLM, okey, r);
            float area = fmaxf(bx.z - bx.x, 0.f) * fmaxf(bx.w - bx.y, 0.f);

            bool supme = false;
            if (lane < kc) {
                float iy1 = fmaxf(bx.x, mykept.x), ix1 = fmaxf(bx.y, mykept.y);
                float iy2 = fminf(bx.z, mykept.z), ix2 = fminf(bx.w, mykept.w);
                float inter = fmaxf(iy2 - iy1, 0.f) * fmaxf(ix2 - ix1, 0.f);
                float uni = area + myka - inter;
                float iou = (uni > 0.f) ? inter / uni : 0.f;
                supme = iou > 0.5f;
            }
            bool keep = (__ballot_sync(FULLM, supme) == 0u);

            if (keep) {
                if (lane == kc) {
                    mykept = bx; myka = area;
                    int flat = c * KCAND + totpops + r;
                    int pos  = c * MAXPC + kc;
                    g_keys[b * NCLS * MAXPC + pos] =
                        ((u64)(u32)(key >> 32) << 32) |
                        ((u64)(u32)(0x7FFF - flat) << 16) | (u32)pos;
                    g_boxes[b * NCLS * MAXPC + pos] = bx;
                }
                ++kc;
                if (kc >= MAXPC) return kc;
            }
        }
        totpops += n;
    }
    return kc;
}

// ---------------------------------------------------------------------------
// Fused kernel: scan -> grid barrier -> per-warp NMS -> per-batch counters ->
// CTA0 per-batch finishers (start as soon as their batch completes).
// 592 CTAs, all co-resident (4/SM exactly).
// ---------------------------------------------------------------------------
__global__ void __launch_bounds__(256, 4) fused_kernel(
    const float4* __restrict__ boxes4,
    const float*  __restrict__ scores,
    float* __restrict__ out,
    int nbox, int chunk, int force_fb)
{
    const int tid  = threadIdx.x;
    const int lane = tid & 31;
    const int wid  = tid >> 5;
    const u32 grid = gridDim.x;

    __shared__ u32 sh_loc[NCLS * LOCCAP];    // 2.5 KB
    __shared__ int sh_lcnt[NCLS];
    __shared__ int sh_fc[8];

    // ======== phase 1: coalesced scan, 8 independent loads in flight ========
    {
        const int b    = blockIdx.x / NCHUNKS;
        const int ch   = blockIdx.x % NCHUNKS;
        const int box0 = ch * chunk;
        const int boxN = min(chunk, nbox - box0);

        for (int i = tid; i < NCLS; i += 256) sh_lcnt[i] = 0;
        __syncthreads();

        if (boxN > 0) {
            const float4* sp = reinterpret_cast<const float4*>(scores) +
                               (size_t)(b * nbox + box0) * (NCLS / 4);
            const int nf4 = boxN * (NCLS / 4);
            for (int t0 = tid; t0 < nf4; t0 += 256 * UNR) {
                float4 v[UNR];
                #pragma unroll
                for (int u = 0; u < UNR; ++u) {
                    int t = t0 + u * 256;
                    v[u] = (t < nf4) ? __ldcs(sp + t)
                                     : make_float4(0.f, 0.f, 0.f, 0.f);
                }
                #pragma unroll
                for (int u = 0; u < UNR; ++u) {
                    float m = fmaxf(fmaxf(v[u].x, v[u].y), fmaxf(v[u].z, v[u].w));
                    if (m >= THR) {   // rare (~0.64% of float4s)
                        int t = t0 + u * 256;
                        int box = box0 + t / (NCLS / 4);
                        int g   = t % (NCLS / 4);
                        float sv[4] = {v[u].x, v[u].y, v[u].z, v[u].w};
                        #pragma unroll
                        for (int k = 0; k < 4; ++k) {
                            if (sv[k] >= THR) {
                                int c = g * 4 + k;
                                u32 key = ((__float_as_uint(sv[k]) - SBASE) << 15) |
                                          (u32)(0x7FFF - box);
                                int p = atomicAdd(&sh_lcnt[c], 1);
                                if (p < LOCCAP) {
                                    sh_loc[c * LOCCAP + p] = key;
                                } else {  // rare spill (set stays complete)
                                    int q = atomicAdd(&g_cnt[b * NCLS + c], 1);
                                    if (q < CAPSC)
                                        g_cand[(size_t)(b * NCLS + c) * CSTRIDE32 + q] = key;
                                }
                            }
                        }
                    }
                }
            }
        }
        __syncthreads();

        for (int c = tid; c < NCLS; c += 256) {
            int n = min(sh_lcnt[c], LOCCAP);
            if (n > 0) {
                int base = atomicAdd(&g_cnt[b * NCLS + c], n);
                for (int j = 0; j < n; ++j) {
                    int q = base + j;
                    if (q < CAPSC)
                        g_cand[(size_t)(b * NCLS + c) * CSTRIDE32 + q] =
                            sh_loc[c * LOCCAP + j];
                }
            }
        }
    }

    grid_barrier(&g_bar1, grid);

    // ======== phase 2: per-warp NMS (first 640 warps) ========
    const int gw = blockIdx.x * 8 + wid;
    if (gw < NCLASSES) {
        const int cls = gw;
        const int b   = cls / NCLS;
        const int c   = cls % NCLS;
        const u32* cand32 = g_cand + (size_t)cls * CSTRIDE32;
        int cnt = g_cnt[cls];
        int kc = 0;
        bool needfb = force_fb || (cnt > CAPSC) || (cnt <= 0);

        if (!needfb) {
            bool ranout = false;
            kc = nms_sorted(boxes4, nbox, b, c, cand32, cnt, &ranout);
            needfb = ranout;
        }

        if (needfb) {
            // exact histogram rescan in GLOBAL scratch (never expected)
            u64* cand64 = (u64*)cand32;
            u32* hist = g_hist + (size_t)cls * NBUCKETS;
            for (int i = lane; i < NBUCKETS; i += 32) hist[i] = 0;
            __syncwarp();
            for (int i = lane; i < nbox; i += 32) {
                float s = scores[((size_t)b * nbox + i) * NCLS + c];
                atomicAdd(&hist[min((int)(s * (float)NBUCKETS), NBUCKETS - 1)], 1u);
            }
            __syncwarp();
            const int base = lane * 32;
            u32 part = 0;
            #pragma unroll
            for (int j = 0; j < 32; ++j) part += hist[base + j];
            u32 suf = part;
            #pragma unroll
            for (int off = 16; off; off >>= 1) {
                u32 vv = __shfl_down_sync(FULLM, suf, off);
                if (lane + off < 32) suf += vv;
            }
            u32 above = __shfl_down_sync(FULLM, suf, 1);
            if (lane == 31) above = 0;
            int T = -1;
            u32 prev = above;
            for (int bkt = base + 31; bkt >= base; --bkt) {
                u32 cur = prev + hist[bkt];
                if (cur >= KCAND && prev < KCAND) T = bkt;
                prev = cur;
            }
            #pragma unroll
            for (int off = 16; off; off >>= 1)
                T = max(T, __shfl_xor_sync(FULLM, T, off));
            T = max(T, 0);
            if (lane == 0) sh_fc[wid] = 0;
            __syncwarp();
            for (int i = lane; i < nbox; i += 32) {
                float s = scores[((size_t)b * nbox + i) * NCLS + c];
                int bk = min((int)(s * (float)NBUCKETS), NBUCKETS - 1);
                if (bk >= T) {
                    int q = atomicAdd(&sh_fc[wid], 1);
                    if (q < KRF * 32)
                        cand64[q] = ((u64)__float_as_uint(s) << 32) |
                                    (u32)(0xFFFFFFFFu - (u32)i);
                }
            }
            __threadfence();
            __syncwarp();
            int fcnt = min(sh_fc[wid], KRF * 32);
            kc = run_nms_fb(boxes4, nbox, b, c, cand64, fcnt);
        }

        if (lane >= kc && lane < MAXPC)
            g_keys[(size_t)cls * MAXPC + lane] = 0ull;

        // signal this batch's completion counter
        if (lane == 0) {
            __threadfence();
            atomicAdd(&g_nmsdone[b], 1);
        }
    }

    if (blockIdx.x != 0) return;    // everyone but CTA0 retires now

    // ======== phase 3: CTA0, warp bb finishes batch bb as soon as ready =====
    {
        const int bb = wid;   // 8 warps == 8 batches
        while (((volatile int*)g_nmsdone)[bb] < NCLS) __nanosleep(64);
        __syncwarp();
        __threadfence();      // acquire g_keys/g_boxes for this batch

        u64 t[8] = {0, 0, 0, 0, 0, 0, 0, 0};
        #pragma unroll
        for (int j = 0; j < 20; ++j) {
            u64 k = g_keys[(size_t)bb * (NCLS * MAXPC) + j * 32 + lane];
            if (k > t[7]) {
                #pragma unroll
                for (int p = 0; p < 8; ++p)
                    if (k > t[p]) { u64 tmp = t[p]; t[p] = k; k = tmp; }
            }
        }

        u64 mykey = 0ull;
        #pragma unroll
        for (int r = 0; r < 8; ++r) {
            u64 best = warpmax64(t[0]);
            if (lane == r) mykey = best;
            if (t[0] == best) {
                #pragma unroll
                for (int p = 0; p < 7; ++p) t[p] = t[p + 1];
                t[7] = 0ull;
            }
        }

        float s = __uint_as_float((u32)(mykey >> 32));
        bool mask = s > 0.0f;
        if (lane < 8) {
            float4 bx = make_float4(0.f, 0.f, 0.f, 0.f);
            float fcls = 0.f;
            if (mask) {
                int pos  = (int)(mykey & 0xFFFFu);
                int flat = 0x7FFF - (int)((mykey >> 16) & 0x7FFFu);
                fcls = (float)(flat / KCAND);
                float4 gb = g_boxes[(size_t)bb * (NCLS * MAXPC) + pos];
                bx.x = clamp01(gb.x); bx.y = clamp01(gb.y);
                bx.z = clamp01(gb.z); bx.w = clamp01(gb.w);
            }
            int ob = (bb * 8 + lane) * 4;
            out[ob + 0] = bx.x; out[ob + 1] = bx.y;
            out[ob + 2] = bx.z; out[ob + 3] = bx.w;
            out[NB * 8 * 4 + bb * 8 + lane]          = mask ? s : 0.f;    // scores  @256
            out[NB * 8 * 4 + NB * 8 + bb * 8 + lane] = mask ? fcls : 0.f; // classes @320
        }
        u32 vb = __ballot_sync(FULLM, (lane < 8) && mask);
        if (lane == 0)
            out[NB * 8 * 4 + 2 * NB * 8 + bb] = (float)__popc(vb);        // valid @384
    }

    // reset scratch for the next graph replay
    __syncthreads();
    if (tid == 0) g_bar1 = 0;
    if (tid < NB) g_nmsdone[tid] = 0;
    for (int i = tid; i < NCLASSES; i += 256) g_cnt[i] = 0;
}

// ---------------------------------------------------------------------------
extern "C" void kernel_launch(void* const* d_in, const int* in_sizes, int n_in,
                              void* d_out, int out_size)
{
    const float* boxes  = (const float*)d_in[0];
    const float* scores = (const float*)d_in[1];
    int nbox = in_sizes[0] / (NB * 4);
    int chunk = (nbox + NCHUNKS - 1) / NCHUNKS;   // grid FIXED at 592 CTAs
    int force_fb = (nbox > 32767) ? 1 : 0;

    fused_kernel<<<NB * NCHUNKS, 256>>>((const float4*)boxes, scores,
                                        (float*)d_out, nbox, chunk, force_fb);
}